// round 2
// baseline (speedup 1.0000x reference)
#include <cuda_runtime.h>
#include <cstdint>

#define BB 16384
#define FF 50
#define EE 64

// Scratch for the stage-1 intermediate h_out [B,F,E] (~210MB).
// __device__ global = the sanctioned no-allocation scratch mechanism.
__device__ float g_ho[(size_t)BB * FF * EE];

// ---------------- packed f32x2 FMA helpers (FFMA2, PTX-only path) ----------
__device__ __forceinline__ unsigned long long pack2(float lo, float hi) {
    unsigned long long r;
    asm("mov.b64 %0, {%1, %2};" : "=l"(r) : "f"(lo), "f"(hi));
    return r;
}
__device__ __forceinline__ unsigned long long ffma2(unsigned long long a,
                                                    unsigned long long b,
                                                    unsigned long long c) {
    unsigned long long d;
    asm("fma.rn.f32x2 %0, %1, %2, %3;" : "=l"(d) : "l"(a), "l"(b), "l"(c));
    return d;
}
__device__ __forceinline__ float2 unpack2(unsigned long long v) {
    float2 f;
    asm("mov.b64 {%0, %1}, %2;" : "=f"(f.x), "=f"(f.y) : "l"(v));
    return f;
}

// ---------------------------------------------------------------------------
// Stage 1 / Stage 3: per-field GEMM.
//   Y[b,f,i] = sum_j W[f,i,j] * X[b,f,j]   (+ bias[i] if ADD_BIAS)
// Grid (B/128, F), 256 threads. CTA tile 128(b) x 64(i), K=64 resident.
// Thread tile 4b x 8i = 16 ffma2 per k.
// ADD_BIAS variant runs IN-PLACE on d_out: the X tile is fully staged into
// smem before any global write, and CTAs touch disjoint tiles.
// ---------------------------------------------------------------------------
#define XSTR 68  // smem row stride (floats); 68*4 = 272 = 17*16 keeps float4 alignment
template <bool ADD_BIAS>
__global__ __launch_bounds__(256) void field_gemm(
    const float* __restrict__ X, const float* __restrict__ W,
    const float* __restrict__ bias, float* __restrict__ Y) {
    extern __shared__ float sm[];
    float* Xs = sm;              // [128][XSTR]  Xs[b][j]
    float* WT = sm + 128 * XSTR; // [64][XSTR]   WT[j][i] = W[f][i][j]

    const int f   = blockIdx.y;
    const int b0  = blockIdx.x * 128;
    const int tid = threadIdx.x;

    // Load X tile: 128 rows x 64 (coalesced float4)
    const float* Xb = X + (size_t)b0 * (FF * EE) + f * EE;
#pragma unroll
    for (int it = 0; it < 8; it++) {
        int idx = tid + it * 256;      // 0..2047 float4s
        int b   = idx >> 4;
        int k4  = idx & 15;
        float4 v = *reinterpret_cast<const float4*>(Xb + (size_t)b * (FF * EE) + k4 * 4);
        *reinterpret_cast<float4*>(&Xs[b * XSTR + k4 * 4]) = v;
    }
    // Load + transpose W[f] (64x64) -> WT[j][i]
    const float* Wf = W + (size_t)f * EE * EE;
#pragma unroll
    for (int it = 0; it < 4; it++) {
        int idx = tid + it * 256;      // 0..1023 float4s
        int i   = idx >> 4;
        int k4  = idx & 15;
        float4 v = *reinterpret_cast<const float4*>(Wf + i * EE + k4 * 4);
        WT[(4 * k4 + 0) * XSTR + i] = v.x;
        WT[(4 * k4 + 1) * XSTR + i] = v.y;
        WT[(4 * k4 + 2) * XSTR + i] = v.z;
        WT[(4 * k4 + 3) * XSTR + i] = v.w;
    }
    __syncthreads();

    const int tx  = tid & 7;    // i-group: i0 = 8*tx
    const int ty  = tid >> 3;   // b-group: bb0 = 4*ty
    const int i0  = tx * 8;
    const int bb0 = ty * 4;

    unsigned long long acc[4][4];
#pragma unroll
    for (int b = 0; b < 4; b++)
#pragma unroll
        for (int p = 0; p < 4; p++) acc[b][p] = 0ULL;

#pragma unroll 4
    for (int j = 0; j < EE; j++) {
        unsigned long long wv[4];
#pragma unroll
        for (int p = 0; p < 4; p++)
            wv[p] = *reinterpret_cast<const unsigned long long*>(&WT[j * XSTR + i0 + 2 * p]);
#pragma unroll
        for (int b = 0; b < 4; b++) {
            float x = Xs[(bb0 + b) * XSTR + j];
            unsigned long long xp = pack2(x, x);
#pragma unroll
            for (int p = 0; p < 4; p++) acc[b][p] = ffma2(xp, wv[p], acc[b][p]);
        }
    }

#pragma unroll
    for (int b = 0; b < 4; b++) {
        float* yrow = Y + (size_t)(b0 + bb0 + b) * (FF * EE) + f * EE + i0;
#pragma unroll
        for (int p = 0; p < 4; p++) {
            float2 r = unpack2(acc[b][p]);
            if (ADD_BIAS) {
                r.x += bias[i0 + 2 * p];
                r.y += bias[i0 + 2 * p + 1];
            }
            *reinterpret_cast<float2*>(yrow + 2 * p) = r;
        }
    }
}

// ---------------------------------------------------------------------------
// Stage 2: per-batch aggregation.
//   out[b,f,e] = sum_g G[b,f,g] * HO[b,g,e]     ([50x50] @ [50x64])
// 2 batches per CTA, 160 threads (80 per batch: 10 f-groups x 8 e-groups).
// Thread tile: 5f x 8e (4 f32x2 pairs). G + HO resident in static smem.
// Writes directly into d_out (stage 3 then runs in-place on d_out).
// ---------------------------------------------------------------------------
__global__ __launch_bounds__(160) void aggr_kernel(
    const float* __restrict__ Gm, const float* __restrict__ HO,
    float* __restrict__ out) {
    __shared__ __align__(16) float HOs[2][FF * EE];   // 2 x 3200
    __shared__ __align__(16) float Gs[2][FF * FF];    // 2 x 2500

    const int b0  = blockIdx.x * 2;
    const int tid = threadIdx.x;

    // Load HO: 2 x 3200 floats = 1600 float4
    for (int idx = tid; idx < 1600; idx += 160) {
        int lb = idx / 800, r = idx - lb * 800;
        *reinterpret_cast<float4*>(&HOs[lb][r * 4]) =
            *reinterpret_cast<const float4*>(HO + (size_t)(b0 + lb) * (FF * EE) + r * 4);
    }
    // Load G: 2 x 2500 floats = 1250 float4
    for (int idx = tid; idx < 1250; idx += 160) {
        int lb = idx / 625, r = idx - lb * 625;
        *reinterpret_cast<float4*>(&Gs[lb][r * 4]) =
            *reinterpret_cast<const float4*>(Gm + (size_t)(b0 + lb) * (FF * FF) + r * 4);
    }
    __syncthreads();

    const int lb = tid / 80;
    const int tl = tid - lb * 80;
    const int eg = tl & 7;    // e0 = 8*eg
    const int fg = tl >> 3;   // f0 = 5*fg  (fg 0..9)
    const int e0 = eg * 8;
    const int f0 = fg * 5;

    unsigned long long acc[5][4];
#pragma unroll
    for (int i = 0; i < 5; i++)
#pragma unroll
        for (int p = 0; p < 4; p++) acc[i][p] = 0ULL;

#pragma unroll 5
    for (int gf = 0; gf < FF; gf++) {
        unsigned long long hv[4];
#pragma unroll
        for (int p = 0; p < 4; p++)
            hv[p] = *reinterpret_cast<const unsigned long long*>(&HOs[lb][gf * EE + e0 + 2 * p]);
#pragma unroll
        for (int i = 0; i < 5; i++) {
            float gval = Gs[lb][(f0 + i) * FF + gf];
            unsigned long long gp = pack2(gval, gval);
#pragma unroll
            for (int p = 0; p < 4; p++) acc[i][p] = ffma2(gp, hv[p], acc[i][p]);
        }
    }

#pragma unroll
    for (int i = 0; i < 5; i++) {
        float* orow = out + (size_t)(b0 + lb) * (FF * EE) + (f0 + i) * EE + e0;
#pragma unroll
        for (int p = 0; p < 4; p++)
            *reinterpret_cast<unsigned long long*>(orow + 2 * p) = acc[i][p];
    }
}

extern "C" void kernel_launch(void* const* d_in, const int* in_sizes, int n_in,
                              void* d_out, int out_size) {
    const float* g     = (const float*)d_in[0];   // [B,F,F]
    const float* h     = (const float*)d_in[1];   // [B,F,E]
    const float* W_in  = (const float*)d_in[2];   // [F,E,E]
    const float* W_out = (const float*)d_in[3];   // [F,E,E]
    const float* bias  = (const float*)d_in[4];   // [E]
    float* out = (float*)d_out;                   // [B,F,E]

    float* ho = nullptr;
    cudaGetSymbolAddress((void**)&ho, g_ho);

    const int smem1 = (128 + 64) * XSTR * (int)sizeof(float);  // 52224 B
    cudaFuncSetAttribute((const void*)field_gemm<false>,
                         cudaFuncAttributeMaxDynamicSharedMemorySize, smem1);
    cudaFuncSetAttribute((const void*)field_gemm<true>,
                         cudaFuncAttributeMaxDynamicSharedMemorySize, smem1);

    // Stage 1: ho = einsum('fij,bfj->bfi', W_out, h)
    field_gemm<false><<<dim3(BB / 128, FF), 256, smem1>>>(h, W_out, nullptr, ho);
    // Stage 2: out = einsum('bfg,bge->bfe', g, ho)
    aggr_kernel<<<BB / 2, 160>>>(g, ho, out);
    // Stage 3 (in-place): out = einsum('fij,bfj->bfi', W_in, out) + bias
    field_gemm<true><<<dim3(BB / 128, FF), 256, smem1>>>(out, W_in, bias, out);
}

// round 3
// speedup vs baseline: 1.2491x; 1.2491x over previous
#include <cuda_runtime.h>
#include <cstdint>

#define BB 16384
#define FF 50
#define EE 64

// Scratch for the stage-1 intermediate h_out [B,F,E] (~210MB).
__device__ float g_ho[(size_t)BB * FF * EE];

typedef unsigned long long ull;

// ---------------- packed f32x2 FMA helpers (FFMA2, PTX-only path) ----------
__device__ __forceinline__ ull pack2(float lo, float hi) {
    ull r;
    asm("mov.b64 %0, {%1, %2};" : "=l"(r) : "f"(lo), "f"(hi));
    return r;
}
__device__ __forceinline__ ull ffma2(ull a, ull b, ull c) {
    ull d;
    asm("fma.rn.f32x2 %0, %1, %2, %3;" : "=l"(d) : "l"(a), "l"(b), "l"(c));
    return d;
}
__device__ __forceinline__ float2 unpack2(ull v) {
    float2 f;
    asm("mov.b64 {%0, %1}, %2;" : "=f"(f.x), "=f"(f.y) : "l"(v));
    return f;
}

// ---------------------------------------------------------------------------
// Stage 1 / Stage 3: per-field GEMM.
//   Y[b,f,i] = sum_j W[f,i,j] * X[b,f,j]   (+ bias[i] if ADD_BIAS)
// Grid (B/128, F), 256 threads. CTA tile 128(b) x 64(i), K=64 resident.
// Thread tile 4b x 8i (two 4-wide i chunks at i0 and 32+i0).
//   - Xs [128][64]: chunk-XOR-swizzled by (b>>2)&7 -> x fetched via LDS.128,
//     conflict-free across the 4 ty-rows of a warp.
//   - WT [64][68]:  W transposed; wv fetched via 2x LDS.128 (ulonglong2),
//     lanes tx*16B apart -> conflict-free. Transpose store uses lane-spread
//     i = tid&63 -> conflict-free STS.32 (W is tiny + L2-resident, the
//     uncoalesced LDG is negligible).
// ADD_BIAS variant runs IN-PLACE on d_out (tile fully staged to smem before
// any write; CTAs touch disjoint tiles -> race-free, graph-replay safe).
// ---------------------------------------------------------------------------
#define WSTR 68  // 68*4B = 272B = 17*16 -> rows stay 16B-aligned for LDS.128

template <bool ADD_BIAS>
__global__ __launch_bounds__(256) void field_gemm(
    const float* __restrict__ X, const float* __restrict__ W,
    const float* __restrict__ bias, float* __restrict__ Y) {
    extern __shared__ float sm[];
    float* Xs = sm;               // [128][64], swizzled chunks
    float* WT = sm + 128 * 64;    // [64][WSTR], WT[j][i] = W[f][i][j]

    const int f   = blockIdx.y;
    const int b0  = blockIdx.x * 128;
    const int tid = threadIdx.x;

    // Load X tile (coalesced float4), store with chunk swizzle.
    const float* Xb = X + (size_t)b0 * (FF * EE) + (size_t)f * EE;
#pragma unroll
    for (int it = 0; it < 8; it++) {
        int idx = tid + it * 256;        // 0..2047
        int b   = idx >> 4;
        int c   = idx & 15;
        int cp  = c ^ ((b >> 2) & 7);
        float4 v = *reinterpret_cast<const float4*>(Xb + (size_t)b * (FF * EE) + c * 4);
        *reinterpret_cast<float4*>(Xs + b * 64 + cp * 4) = v;
    }
    // Load + transpose W[f]: lane-spread i for conflict-free STS.
    {
        const float* Wf = W + (size_t)f * EE * EE;
        int i   = tid & 63;
        int j4b = tid >> 6;              // 0..3
#pragma unroll
        for (int it = 0; it < 4; it++) {
            int j4 = j4b + it * 4;       // 0..15
            float4 v = *reinterpret_cast<const float4*>(Wf + i * EE + j4 * 4);
            WT[(4 * j4 + 0) * WSTR + i] = v.x;
            WT[(4 * j4 + 1) * WSTR + i] = v.y;
            WT[(4 * j4 + 2) * WSTR + i] = v.z;
            WT[(4 * j4 + 3) * WSTR + i] = v.w;
        }
    }
    __syncthreads();

    const int tx  = tid & 7;
    const int ty  = tid >> 3;
    const int i0  = tx * 4;      // i chunks: [i0, i0+3] and [32+i0, 32+i0+3]
    const int bb0 = ty * 4;
    const int xsw = ty & 7;

    ull acc[4][4];
#pragma unroll
    for (int b = 0; b < 4; b++)
#pragma unroll
        for (int p = 0; p < 4; p++) acc[b][p] = 0ULL;

#pragma unroll 2
    for (int j0 = 0; j0 < EE; j0 += 4) {
        float4 xv[4];
#pragma unroll
        for (int bi = 0; bi < 4; bi++)
            xv[bi] = *reinterpret_cast<const float4*>(
                Xs + (bb0 + bi) * 64 + (((j0 >> 2) ^ xsw) << 2));
#pragma unroll
        for (int jq = 0; jq < 4; jq++) {
            const float* wr = WT + (j0 + jq) * WSTR;
            ulonglong2 wa = *reinterpret_cast<const ulonglong2*>(wr + i0);
            ulonglong2 wb = *reinterpret_cast<const ulonglong2*>(wr + 32 + i0);
#pragma unroll
            for (int bi = 0; bi < 4; bi++) {
                float x = (jq == 0) ? xv[bi].x : (jq == 1) ? xv[bi].y
                        : (jq == 2) ? xv[bi].z : xv[bi].w;
                ull xp = pack2(x, x);
                acc[bi][0] = ffma2(xp, wa.x, acc[bi][0]);
                acc[bi][1] = ffma2(xp, wa.y, acc[bi][1]);
                acc[bi][2] = ffma2(xp, wb.x, acc[bi][2]);
                acc[bi][3] = ffma2(xp, wb.y, acc[bi][3]);
            }
        }
    }

    float4 bv0 = make_float4(0.f, 0.f, 0.f, 0.f);
    float4 bv1 = bv0;
    if (ADD_BIAS) {
        bv0 = *reinterpret_cast<const float4*>(bias + i0);
        bv1 = *reinterpret_cast<const float4*>(bias + 32 + i0);
    }

#pragma unroll
    for (int bi = 0; bi < 4; bi++) {
        float* yrow = Y + (size_t)(b0 + bb0 + bi) * (FF * EE) + (size_t)f * EE;
        float2 a0 = unpack2(acc[bi][0]), a1 = unpack2(acc[bi][1]);
        float2 a2 = unpack2(acc[bi][2]), a3 = unpack2(acc[bi][3]);
        float4 r0 = make_float4(a0.x + bv0.x, a0.y + bv0.y, a1.x + bv0.z, a1.y + bv0.w);
        float4 r1 = make_float4(a2.x + bv1.x, a2.y + bv1.y, a3.x + bv1.z, a3.y + bv1.w);
        *reinterpret_cast<float4*>(yrow + i0)      = r0;
        *reinterpret_cast<float4*>(yrow + 32 + i0) = r1;
    }
}

// ---------------------------------------------------------------------------
// Stage 2: per-batch aggregation.
//   out[b,f,e] = sum_g G[b,f,g] * HO[b,g,e]     ([50x50] @ [50x64])
// 2 batches per CTA, 256 threads (128 = 4 full warps per batch).
// Thread tile 4f x 8e. Per gf: 2x LDS.128 (hv, via even/odd chunk permutation,
// conflict-free) + 1x LDS.128 (g fragment from transposed+chunk-swizzled Gs,
// conflict-free) feeding 16 FFMA2 -> FFMA-bound.
// fg in [0,12]; fg==12 computes 2 valid f rows (store-guarded); fg>=13 idle.
// Writes directly into d_out (stage 3 then runs in-place on d_out).
// ---------------------------------------------------------------------------
__global__ __launch_bounds__(256) void aggr_kernel(
    const float* __restrict__ Gm, const float* __restrict__ HO,
    float* __restrict__ out) {
    extern __shared__ float sm2[];
    float* HOs = sm2;                 // [2][50*64], chunk-permuted rows
    float* Gs  = sm2 + 2 * FF * EE;   // [2][50*64], Gs[g][f] chunk-swizzled

    const int b0  = blockIdx.x * 2;
    const int tid = threadIdx.x;

    // HO: 2 x 800 float4, store with even/odd chunk permutation:
    //   pos = (c>>1) | ((c&1)<<3)  -> chunk 2*eg lands at pos eg, 2*eg+1 at eg+8
    for (int idx = tid; idx < 1600; idx += 256) {
        int lb = (idx >= 800);
        int r  = idx - lb * 800;       // r = g*16 + c
        int g  = r >> 4;
        int c  = r & 15;
        int pos = (c >> 1) | ((c & 1) << 3);
        float4 v = *reinterpret_cast<const float4*>(
            HO + (size_t)(b0 + lb) * (FF * EE) + r * 4);
        *reinterpret_cast<float4*>(HOs + lb * (FF * EE) + g * 64 + pos * 4) = v;
    }
    // G: scalar transpose Gs[g][f] with chunk swizzle (f-chunk c -> c ^ (g&15)).
    for (int idx = tid; idx < 2 * FF * FF; idx += 256) {
        int lb = (idx >= FF * FF);
        int r  = idx - lb * (FF * FF);
        int fq = r / FF;
        int gq = r - fq * FF;
        float v = Gm[(size_t)(b0 + lb) * (FF * FF) + r];
        int chunk = (fq >> 2) ^ (gq & 15);
        Gs[lb * (FF * EE) + gq * 64 + chunk * 4 + (fq & 3)] = v;
    }
    __syncthreads();

    const int lb = tid >> 7;
    const int t  = tid & 127;
    const int eg = t & 7;
    const int fg = t >> 3;             // 0..15
    if (fg >= 13) return;
    const int f0 = fg * 4;

    const float* hb = HOs + lb * (FF * EE);
    const float* gb = Gs  + lb * (FF * EE);

    ull acc[4][4];
#pragma unroll
    for (int q = 0; q < 4; q++)
#pragma unroll
        for (int p = 0; p < 4; p++) acc[q][p] = 0ULL;

#pragma unroll 2
    for (int gf = 0; gf < FF; gf++) {
        ulonglong2 h0 = *reinterpret_cast<const ulonglong2*>(hb + gf * 64 + eg * 4);
        ulonglong2 h1 = *reinterpret_cast<const ulonglong2*>(hb + gf * 64 + (8 + eg) * 4);
        float4 gv = *reinterpret_cast<const float4*>(
            gb + gf * 64 + ((fg ^ (gf & 15)) << 2));
#pragma unroll
        for (int q = 0; q < 4; q++) {
            float gval = (q == 0) ? gv.x : (q == 1) ? gv.y : (q == 2) ? gv.z : gv.w;
            ull gp = pack2(gval, gval);
            acc[q][0] = ffma2(gp, h0.x, acc[q][0]);
            acc[q][1] = ffma2(gp, h0.y, acc[q][1]);
            acc[q][2] = ffma2(gp, h1.x, acc[q][2]);
            acc[q][3] = ffma2(gp, h1.y, acc[q][3]);
        }
    }

#pragma unroll
    for (int q = 0; q < 4; q++) {
        if (f0 + q < FF) {
            float* orow = out + (size_t)(b0 + lb) * (FF * EE) + (f0 + q) * EE + eg * 8;
            float2 a0 = unpack2(acc[q][0]), a1 = unpack2(acc[q][1]);
            float2 a2 = unpack2(acc[q][2]), a3 = unpack2(acc[q][3]);
            *reinterpret_cast<float4*>(orow)     = make_float4(a0.x, a0.y, a1.x, a1.y);
            *reinterpret_cast<float4*>(orow + 4) = make_float4(a2.x, a2.y, a3.x, a3.y);
        }
    }
}

extern "C" void kernel_launch(void* const* d_in, const int* in_sizes, int n_in,
                              void* d_out, int out_size) {
    const float* g     = (const float*)d_in[0];   // [B,F,F]
    const float* h     = (const float*)d_in[1];   // [B,F,E]
    const float* W_in  = (const float*)d_in[2];   // [F,E,E]
    const float* W_out = (const float*)d_in[3];   // [F,E,E]
    const float* bias  = (const float*)d_in[4];   // [E]
    float* out = (float*)d_out;                   // [B,F,E]

    float* ho = nullptr;
    cudaGetSymbolAddress((void**)&ho, g_ho);

    const int smem1 = (128 * 64 + 64 * WSTR) * (int)sizeof(float);  // 50176 B
    const int smem2 = 4 * FF * EE * (int)sizeof(float);             // 51200 B
    cudaFuncSetAttribute((const void*)field_gemm<false>,
                         cudaFuncAttributeMaxDynamicSharedMemorySize, smem1);
    cudaFuncSetAttribute((const void*)field_gemm<true>,
                         cudaFuncAttributeMaxDynamicSharedMemorySize, smem1);
    cudaFuncSetAttribute((const void*)aggr_kernel,
                         cudaFuncAttributeMaxDynamicSharedMemorySize, smem2);

    // Stage 1: ho = einsum('fij,bfj->bfi', W_out, h)
    field_gemm<false><<<dim3(BB / 128, FF), 256, smem1>>>(h, W_out, nullptr, ho);
    // Stage 2: out = einsum('bfg,bge->bfe', g, ho)
    aggr_kernel<<<BB / 2, 256, smem2>>>(g, ho, out);
    // Stage 3 (in-place): out = einsum('fij,bfj->bfi', W_in, out) + bias
    field_gemm<true><<<dim3(BB / 128, FF), 256, smem1>>>(out, W_in, bias, out);
}